// round 2
// baseline (speedup 1.0000x reference)
#include <cuda_runtime.h>
#include <cstdint>

// Output layout (fp32):
//   [0, U*64)             user_emb1  = all_emb1[:U]
//   [U*64, N*64)          item_emb1  = all_emb1[U:]
//   [N*64, (N+U)*64)      user_emb2
//   [(N+U)*64, (N+U+I)*64) item_emb2
// Graph SpMM writes directly into out[0 : N*64).

#define TPB 256
#define D64 64
#define EPT 4   // edges per thread (MLP factor)

struct Args {
    const int*   g_rows; const int* g_cols; const float* g_vals;
    const int*   u_rows; const int* u_cols; const float* u_vals;
    const int*   i_rows; const int* i_cols; const float* i_vals;
    const float* user_emb; const float* item_emb;
    float* out;
    int EG, EU, EI, U, N;
};

__global__ void __launch_bounds__(TPB) spmm_fused(Args a) {
    const int ET = a.EG + a.EU + a.EI;
    long long slot   = (long long)blockIdx.x * TPB + threadIdx.x;
    long long stride = (long long)gridDim.x * TPB;   // multiple of 16
    const int lane   = (int)(slot & 15);

    int          eidx[EPT];
    const float* srow[EPT];
    float*       drow[EPT];
    float        val [EPT];
    bool         ok  [EPT];

    // Phase 1: resolve indices for all EPT edges (independent loads).
    #pragma unroll
    for (int k = 0; k < EPT; k++) {
        long long s = slot + (long long)k * stride;
        int e = (int)(s >> 4);
        ok[k] = (e < ET);
        eidx[k] = e;
        srow[k] = nullptr; drow[k] = nullptr; val[k] = 0.f;
        if (ok[k]) {
            int r, c;
            if (e < a.EG) {
                r = a.g_rows[e]; c = a.g_cols[e]; val[k] = a.g_vals[e];
                drow[k] = a.out + (long long)r * D64;
                srow[k] = (c < a.U) ? (a.user_emb + (long long)c * D64)
                                    : (a.item_emb + (long long)(c - a.U) * D64);
            } else if (e < a.EG + a.EU) {
                int eu = e - a.EG;
                r = a.u_rows[eu]; c = a.u_cols[eu]; val[k] = a.u_vals[eu];
                drow[k] = a.out + (long long)(a.N + r) * D64;
                srow[k] = a.user_emb + (long long)c * D64;
            } else {
                int ei = e - a.EG - a.EU;
                r = a.i_rows[ei]; c = a.i_cols[ei]; val[k] = a.i_vals[ei];
                drow[k] = a.out + (long long)(a.N + a.U + r) * D64;
                srow[k] = a.item_emb + (long long)c * D64;
            }
        }
    }

    // Phase 2: issue all gathers (independent -> MLP=EPT).
    float4 x[EPT];
    #pragma unroll
    for (int k = 0; k < EPT; k++) {
        if (ok[k]) {
            x[k] = *(reinterpret_cast<const float4*>(srow[k]) + lane);
        }
    }

    // Phase 3: scale + fire-and-forget vector reductions.
    #pragma unroll
    for (int k = 0; k < EPT; k++) {
        if (ok[k]) {
            float4 y = x[k];
            float v = val[k];
            y.x *= v; y.y *= v; y.z *= v; y.w *= v;
            float4* d = reinterpret_cast<float4*>(drow[k]) + lane;
            asm volatile("red.global.add.v4.f32 [%0], {%1,%2,%3,%4};"
                         :: "l"(d), "f"(y.x), "f"(y.y), "f"(y.z), "f"(y.w)
                         : "memory");
        }
    }
}

extern "C" void kernel_launch(void* const* d_in, const int* in_sizes, int n_in,
                              void* d_out, int out_size) {
    Args a;
    a.user_emb = (const float*)d_in[0];
    a.item_emb = (const float*)d_in[1];
    a.g_rows = (const int*)d_in[2];  a.g_cols = (const int*)d_in[3];  a.g_vals = (const float*)d_in[4];
    a.u_rows = (const int*)d_in[5];  a.u_cols = (const int*)d_in[6];  a.u_vals = (const float*)d_in[7];
    a.i_rows = (const int*)d_in[8];  a.i_cols = (const int*)d_in[9];  a.i_vals = (const float*)d_in[10];
    a.out = (float*)d_out;

    a.U = in_sizes[0] / D64;
    const int I_ = in_sizes[1] / D64;
    a.N = a.U + I_;
    a.EG = in_sizes[2];
    a.EU = in_sizes[5];
    a.EI = in_sizes[8];

    cudaMemsetAsync(d_out, 0, (size_t)out_size * sizeof(float), 0);

    const long long ET = (long long)a.EG + a.EU + a.EI;
    const long long slots = ET * 16;
    const long long threads_needed = (slots + EPT - 1) / EPT;
    int blocks = (int)((threads_needed + TPB - 1) / TPB);

    spmm_fused<<<blocks, TPB>>>(a);
}

// round 3
// speedup vs baseline: 1.1427x; 1.1427x over previous
#include <cuda_runtime.h>
#include <cstdint>
#include <climits>

// Output layout (fp32):
//   [0, U*64)              user_emb1 = all_emb1[:U]
//   [U*64, N*64)           item_emb1 = all_emb1[U:]
//   [N*64, (N+U)*64)       user_emb2
//   [(N+U)*64, (N+U+I)*64) item_emb2
// Graph SpMM writes directly into out[0 : N*64).

#define TPB 256
#define D64 64
#define EPT 4   // edges per thread (independent gather chains)

// Unified SpMM: src is logical concat(src0, src1) split at U_split.
// For plain SpMM pass src1 = src0 and U_split = INT_MAX.
__global__ void __launch_bounds__(TPB) spmm_mlp(const int* __restrict__ rows,
                                                const int* __restrict__ cols,
                                                const float* __restrict__ vals,
                                                const float* __restrict__ src0,
                                                const float* __restrict__ src1,
                                                float* __restrict__ dst,
                                                int n_edges, int U_split) {
    long long slot   = (long long)blockIdx.x * TPB + threadIdx.x;
    long long stride = (long long)gridDim.x * TPB;   // multiple of 16
    const int lane   = (int)(slot & 15);

    const float4* s[EPT];
    float4*       d[EPT];
    float         v[EPT];
    bool          ok[EPT];

    // Phase 1: resolve all EPT edge descriptors (independent loads).
    #pragma unroll
    for (int k = 0; k < EPT; k++) {
        int e = (int)((slot + (long long)k * stride) >> 4);
        ok[k] = (e < n_edges);
        if (ok[k]) {
            int r = rows[e];
            int c = cols[e];
            v[k] = vals[e];
            const float* sr = (c < U_split)
                                ? (src0 + (long long)c * D64)
                                : (src1 + (long long)(c - U_split) * D64);
            s[k] = reinterpret_cast<const float4*>(sr) + lane;
            d[k] = reinterpret_cast<float4*>(dst + (long long)r * D64) + lane;
        }
    }

    // Phase 2: issue all gathers (MLP = EPT).
    float4 x[EPT];
    #pragma unroll
    for (int k = 0; k < EPT; k++) {
        if (ok[k]) x[k] = *s[k];
    }

    // Phase 3: scale + fire-and-forget vector reductions.
    #pragma unroll
    for (int k = 0; k < EPT; k++) {
        if (ok[k]) {
            float4 y = x[k];
            y.x *= v[k]; y.y *= v[k]; y.z *= v[k]; y.w *= v[k];
            asm volatile("red.global.add.v4.f32 [%0], {%1,%2,%3,%4};"
                         :: "l"(d[k]), "f"(y.x), "f"(y.y), "f"(y.z), "f"(y.w)
                         : "memory");
        }
    }
}

static inline int blocks_for(long long n_edges) {
    long long slots = n_edges * 16;
    long long threads_needed = (slots + EPT - 1) / EPT;
    return (int)((threads_needed + TPB - 1) / TPB);
}

extern "C" void kernel_launch(void* const* d_in, const int* in_sizes, int n_in,
                              void* d_out, int out_size) {
    const float* user_emb = (const float*)d_in[0];
    const float* item_emb = (const float*)d_in[1];
    const int*   g_rows = (const int*)d_in[2];
    const int*   g_cols = (const int*)d_in[3];
    const float* g_vals = (const float*)d_in[4];
    const int*   u_rows = (const int*)d_in[5];
    const int*   u_cols = (const int*)d_in[6];
    const float* u_vals = (const float*)d_in[7];
    const int*   i_rows = (const int*)d_in[8];
    const int*   i_cols = (const int*)d_in[9];
    const float* i_vals = (const float*)d_in[10];

    float* out = (float*)d_out;

    const int U_ = in_sizes[0] / D64;   // 100000
    const int I_ = in_sizes[1] / D64;   // 50000
    const int N_ = U_ + I_;
    const int EG = in_sizes[2];
    const int EU = in_sizes[5];
    const int EI = in_sizes[8];

    cudaMemsetAsync(d_out, 0, (size_t)out_size * sizeof(float), 0);

    float* dst_graph = out;                               // all_emb1
    float* dst_user2 = out + (long long)N_ * D64;         // user_emb2
    float* dst_item2 = out + (long long)(N_ + U_) * D64;  // item_emb2

    spmm_mlp<<<blocks_for(EG), TPB>>>(g_rows, g_cols, g_vals,
                                      user_emb, item_emb,
                                      dst_graph, EG, U_);

    spmm_mlp<<<blocks_for(EU), TPB>>>(u_rows, u_cols, u_vals,
                                      user_emb, user_emb,
                                      dst_user2, EU, INT_MAX);

    spmm_mlp<<<blocks_for(EI), TPB>>>(i_rows, i_cols, i_vals,
                                      item_emb, item_emb,
                                      dst_item2, EI, INT_MAX);
}